// round 1
// baseline (speedup 1.0000x reference)
#include <cuda_runtime.h>

#define BATCH 128
#define DIN   512
#define HID   1024
#define G4    4096
#define STEPS 64
#define TOFF  55   // (128 - 64 - 9)

typedef unsigned long long ull;

// ---------------- device scratch (no allocations allowed) ----------------
__device__ float g_xproj[(size_t)STEPS * BATCH * G4];   // 128 MB: x@W_ih0^T + b_ih0 + b_hh0
__device__ float g_h0[2][BATCH * HID];                  // ping-pong hidden, layer 0
__device__ float g_h1[2][BATCH * HID];                  // ping-pong hidden, layer 1
__device__ float g_c0[BATCH * HID];
__device__ float g_c1[BATCH * HID];

// ---------------- packed fp32x2 helpers (sm_103a double-rate FMA) --------
__device__ __forceinline__ void fma2(ull& d, ull a, ull b) {
    asm("fma.rn.f32x2 %0, %1, %2, %0;" : "+l"(d) : "l"(a), "l"(b));
}
__device__ __forceinline__ float2 u2f2(ull u) {
    float2 f;
    asm("mov.b64 {%0, %1}, %2;" : "=f"(f.x), "=f"(f.y) : "l"(u));
    return f;
}
__device__ __forceinline__ float sigm(float x) { return 1.0f / (1.0f + expf(-x)); }

// ---------------- init states --------------------------------------------
__global__ void init_states() {
    int i = blockIdx.x * blockDim.x + threadIdx.x;
    if (i < BATCH * HID) {
        g_h0[0][i] = 0.f; g_h1[0][i] = 0.f;
        g_c0[i]    = 0.f; g_c1[i]    = 0.f;
    }
}

// ---------------- xproj: [8192,512] @ [512,4096(W^T)] --------------------
// BM=64 BN=64 BK=16, 256 threads, 4x4 per thread, f32x2 inner loop.
__global__ void __launch_bounds__(256) xproj_kernel(
    const float* __restrict__ xs, const float* __restrict__ Wih0,
    const float* __restrict__ bih0, const float* __restrict__ bhh0)
{
    __shared__ __align__(16) float As[16][64];
    __shared__ __align__(16) float Bs2[16][128];   // replicated pairs {b,b}

    int tid = threadIdx.x;
    int n0 = blockIdx.x * 64, m0 = blockIdx.y * 64;
    int nb = (tid & 15) * 4, mb = (tid >> 4) * 4;

    ull acc[4][2];
#pragma unroll
    for (int i = 0; i < 4; ++i) { acc[i][0] = 0ull; acc[i][1] = 0ull; }

    int lr = tid >> 2, lkc = (tid & 3) * 4;
    int grow = m0 + lr;
    int tt = grow >> 7, bidx = grow & 127;              // row = t*128 + b
    const float* aptr = xs + ((size_t)bidx * 128 + (TOFF + tt)) * DIN + lkc;
    const float* bptr = Wih0 + (size_t)(n0 + lr) * DIN + lkc;

    float4 ra = *(const float4*)aptr;
    float4 rb = *(const float4*)bptr;

#pragma unroll 1
    for (int kt = 0; kt < DIN / 16; ++kt) {
        As[lkc + 0][lr] = ra.x; As[lkc + 1][lr] = ra.y;
        As[lkc + 2][lr] = ra.z; As[lkc + 3][lr] = ra.w;
        Bs2[lkc + 0][2 * lr] = rb.x; Bs2[lkc + 0][2 * lr + 1] = rb.x;
        Bs2[lkc + 1][2 * lr] = rb.y; Bs2[lkc + 1][2 * lr + 1] = rb.y;
        Bs2[lkc + 2][2 * lr] = rb.z; Bs2[lkc + 2][2 * lr + 1] = rb.z;
        Bs2[lkc + 3][2 * lr] = rb.w; Bs2[lkc + 3][2 * lr + 1] = rb.w;
        __syncthreads();
        if (kt + 1 < DIN / 16) {
            int ko = (kt + 1) * 16;
            ra = *(const float4*)(aptr + ko);
            rb = *(const float4*)(bptr + ko);
        }
#pragma unroll
        for (int kk = 0; kk < 16; ++kk) {
            ull a01 = *(const ull*)&As[kk][mb];
            ull a23 = *(const ull*)&As[kk][mb + 2];
#pragma unroll
            for (int ni = 0; ni < 4; ++ni) {
                ull bv = *(const ull*)&Bs2[kk][2 * (nb + ni)];
                fma2(acc[ni][0], a01, bv);
                fma2(acc[ni][1], a23, bv);
            }
        }
        __syncthreads();
    }

#pragma unroll
    for (int ni = 0; ni < 4; ++ni) {
        int n = n0 + nb + ni;
        float bias = bih0[n] + bhh0[n];
        float2 v0 = u2f2(acc[ni][0]);
        float2 v1 = u2f2(acc[ni][1]);
        size_t base = (size_t)(m0 + mb) * G4 + n;
        g_xproj[base          ] = v0.x + bias;
        g_xproj[base +     G4 ] = v0.y + bias;
        g_xproj[base + 2 * G4 ] = v1.x + bias;
        g_xproj[base + 3 * G4 ] = v1.y + bias;
    }
}

// ---------------- recurrent GEMM span: acc += A[128,1024] @ Wrows^T ------
// CTA covers all 128 batch rows x (8 hidden x 4 gates) = 128x32 gate cols.
// Thread: nh_l = tid&7, m_base = (tid>>3)*4; acc[gate][m-pair] as f32x2.
__device__ __forceinline__ void accum_span(
    const float* __restrict__ A, const float* __restrict__ W,
    int nh0, int tid, ull acc[4][2],
    float (*As)[128], float (*Bs2)[64])
{
    int ar = tid >> 2, kc = (tid & 3) * 4;
    const float* aptr0 = A + (size_t)ar * HID + kc;
    const float* aptr1 = aptr0 + (size_t)64 * HID;
    bool bl = tid < 128;
    int br = tid >> 2;                      // 0..31 when bl
    int gate = br >> 3, nh = br & 7;
    const float* bptr = W + (size_t)(gate * HID + nh0 + nh) * HID + kc;

    int m_base = (tid >> 3) * 4;
    int nh_l = tid & 7;

    float4 ra0 = *(const float4*)aptr0;
    float4 ra1 = *(const float4*)aptr1;
    float4 rb = make_float4(0.f, 0.f, 0.f, 0.f);
    if (bl) rb = *(const float4*)bptr;

#pragma unroll 1
    for (int kt = 0; kt < HID / 16; ++kt) {
        As[kc + 0][ar] = ra0.x; As[kc + 1][ar] = ra0.y;
        As[kc + 2][ar] = ra0.z; As[kc + 3][ar] = ra0.w;
        As[kc + 0][ar + 64] = ra1.x; As[kc + 1][ar + 64] = ra1.y;
        As[kc + 2][ar + 64] = ra1.z; As[kc + 3][ar + 64] = ra1.w;
        if (bl) {
            Bs2[kc + 0][2 * br] = rb.x; Bs2[kc + 0][2 * br + 1] = rb.x;
            Bs2[kc + 1][2 * br] = rb.y; Bs2[kc + 1][2 * br + 1] = rb.y;
            Bs2[kc + 2][2 * br] = rb.z; Bs2[kc + 2][2 * br + 1] = rb.z;
            Bs2[kc + 3][2 * br] = rb.w; Bs2[kc + 3][2 * br + 1] = rb.w;
        }
        __syncthreads();
        if (kt + 1 < HID / 16) {
            int ko = (kt + 1) * 16;
            ra0 = *(const float4*)(aptr0 + ko);
            ra1 = *(const float4*)(aptr1 + ko);
            if (bl) rb = *(const float4*)(bptr + ko);
        }
#pragma unroll
        for (int kk = 0; kk < 16; ++kk) {
            ull a01 = *(const ull*)&As[kk][m_base];
            ull a23 = *(const ull*)&As[kk][m_base + 2];
#pragma unroll
            for (int g = 0; g < 4; ++g) {
                ull bv = *(const ull*)&Bs2[kk][2 * (g * 8 + nh_l)];
                fma2(acc[g][0], a01, bv);
                fma2(acc[g][1], a23, bv);
            }
        }
        __syncthreads();
    }
}

// ---------------- layer 0 step: g = xproj[t] + h0@Whh0^T, fused cell -----
__global__ void __launch_bounds__(256) layer0_step(
    const float* __restrict__ Whh0, int t)
{
    __shared__ __align__(16) float As[16][128];
    __shared__ __align__(16) float Bs2[16][64];
    int tid = threadIdx.x;
    int nh0 = blockIdx.x * 8;

    ull acc[4][2];
#pragma unroll
    for (int i = 0; i < 4; ++i) { acc[i][0] = 0ull; acc[i][1] = 0ull; }

    const float* hprev = g_h0[t & 1];
    float* hnew = g_h0[(t + 1) & 1];

    accum_span(hprev, Whh0, nh0, tid, acc, As, Bs2);

    int nh_l = tid & 7, m_base = (tid >> 3) * 4;
    int nhg = nh0 + nh_l;
    const float* xp = g_xproj + (size_t)t * BATCH * G4;

    float vI[4], vF[4], vG[4], vO[4];
    { float2 p0 = u2f2(acc[0][0]), p1 = u2f2(acc[0][1]);
      vI[0]=p0.x; vI[1]=p0.y; vI[2]=p1.x; vI[3]=p1.y; }
    { float2 p0 = u2f2(acc[1][0]), p1 = u2f2(acc[1][1]);
      vF[0]=p0.x; vF[1]=p0.y; vF[2]=p1.x; vF[3]=p1.y; }
    { float2 p0 = u2f2(acc[2][0]), p1 = u2f2(acc[2][1]);
      vG[0]=p0.x; vG[1]=p0.y; vG[2]=p1.x; vG[3]=p1.y; }
    { float2 p0 = u2f2(acc[3][0]), p1 = u2f2(acc[3][1]);
      vO[0]=p0.x; vO[1]=p0.y; vO[2]=p1.x; vO[3]=p1.y; }

#pragma unroll
    for (int mi = 0; mi < 4; ++mi) {
        int m = m_base + mi;
        const float* xr = xp + (size_t)m * G4 + nhg;
        float iv = vI[mi] + xr[0];
        float fv = vF[mi] + xr[1024];
        float gg = vG[mi] + xr[2048];
        float ov = vO[mi] + xr[3072];
        int idx = m * HID + nhg;
        float cn = sigm(fv) * g_c0[idx] + sigm(iv) * tanhf(gg);
        g_c0[idx] = cn;
        hnew[idx] = sigm(ov) * tanhf(cn);
    }
}

// ---------------- layer 1 step: g = b1 + h0new@Wih1^T + h1@Whh1^T --------
__global__ void __launch_bounds__(256) layer1_step(
    const float* __restrict__ Wih1, const float* __restrict__ Whh1,
    const float* __restrict__ bih1, const float* __restrict__ bhh1, int t)
{
    __shared__ __align__(16) float As[16][128];
    __shared__ __align__(16) float Bs2[16][64];
    int tid = threadIdx.x;
    int nh0 = blockIdx.x * 8;

    ull acc[4][2];
#pragma unroll
    for (int i = 0; i < 4; ++i) { acc[i][0] = 0ull; acc[i][1] = 0ull; }

    const float* h0new = g_h0[(t + 1) & 1];
    const float* h1prev = g_h1[t & 1];
    float* h1new = g_h1[(t + 1) & 1];

    accum_span(h0new, Wih1, nh0, tid, acc, As, Bs2);
    accum_span(h1prev, Whh1, nh0, tid, acc, As, Bs2);

    int nh_l = tid & 7, m_base = (tid >> 3) * 4;
    int nhg = nh0 + nh_l;

    float bI = bih1[nhg]            + bhh1[nhg];
    float bF = bih1[HID + nhg]      + bhh1[HID + nhg];
    float bG = bih1[2 * HID + nhg]  + bhh1[2 * HID + nhg];
    float bO = bih1[3 * HID + nhg]  + bhh1[3 * HID + nhg];

    float vI[4], vF[4], vG[4], vO[4];
    { float2 p0 = u2f2(acc[0][0]), p1 = u2f2(acc[0][1]);
      vI[0]=p0.x; vI[1]=p0.y; vI[2]=p1.x; vI[3]=p1.y; }
    { float2 p0 = u2f2(acc[1][0]), p1 = u2f2(acc[1][1]);
      vF[0]=p0.x; vF[1]=p0.y; vF[2]=p1.x; vF[3]=p1.y; }
    { float2 p0 = u2f2(acc[2][0]), p1 = u2f2(acc[2][1]);
      vG[0]=p0.x; vG[1]=p0.y; vG[2]=p1.x; vG[3]=p1.y; }
    { float2 p0 = u2f2(acc[3][0]), p1 = u2f2(acc[3][1]);
      vO[0]=p0.x; vO[1]=p0.y; vO[2]=p1.x; vO[3]=p1.y; }

#pragma unroll
    for (int mi = 0; mi < 4; ++mi) {
        int m = m_base + mi;
        float iv = vI[mi] + bI;
        float fv = vF[mi] + bF;
        float gg = vG[mi] + bG;
        float ov = vO[mi] + bO;
        int idx = m * HID + nhg;
        float cn = sigm(fv) * g_c1[idx] + sigm(iv) * tanhf(gg);
        g_c1[idx] = cn;
        h1new[idx] = sigm(ov) * tanhf(cn);
    }
}

// ---------------- classifier: out = (h1 * keep * 2) @ Wcls^T + bcls ------
// One warp computes one class j for 4 batch rows (W row reuse x4).
__global__ void __launch_bounds__(256) classifier_kernel(
    const float* __restrict__ Wcls, const float* __restrict__ bcls,
    const float* __restrict__ dropu, float* __restrict__ out)
{
    int gw = (blockIdx.x * blockDim.x + threadIdx.x) >> 5;
    int lane = threadIdx.x & 31;
    int j = gw >> 5;            // 0..999
    int b0 = (gw & 31) * 4;     // 0,4,...,124
    const float* h1 = g_h1[0];  // last write: t=63 -> buffer (63+1)&1 = 0

    float acc[4] = {0.f, 0.f, 0.f, 0.f};
#pragma unroll
    for (int it = 0; it < 8; ++it) {
        int h = it * 128 + lane * 4;
        float4 w = *(const float4*)&Wcls[(size_t)j * HID + h];
#pragma unroll
        for (int bi = 0; bi < 4; ++bi) {
            int b = b0 + bi;
            float4 x = *(const float4*)&h1[(size_t)b * HID + h];
            float4 u = *(const float4*)&dropu[(size_t)b * HID + h];
            float s = (u.x > 0.5f ? x.x : 0.f) * w.x
                    + (u.y > 0.5f ? x.y : 0.f) * w.y
                    + (u.z > 0.5f ? x.z : 0.f) * w.z
                    + (u.w > 0.5f ? x.w : 0.f) * w.w;
            acc[bi] += s;
        }
    }
#pragma unroll
    for (int bi = 0; bi < 4; ++bi) {
        float v = acc[bi];
#pragma unroll
        for (int off = 16; off; off >>= 1)
            v += __shfl_xor_sync(0xffffffffu, v, off);
        if (lane == 0)
            out[(size_t)(b0 + bi) * 1000 + j] = 2.0f * v + bcls[j];
    }
}

// ---------------- launch --------------------------------------------------
extern "C" void kernel_launch(void* const* d_in, const int* in_sizes, int n_in,
                              void* d_out, int out_size)
{
    const float* xs    = (const float*)d_in[0];
    const float* Wih0  = (const float*)d_in[1];
    const float* Whh0  = (const float*)d_in[2];
    const float* bih0  = (const float*)d_in[3];
    const float* bhh0  = (const float*)d_in[4];
    const float* Wih1  = (const float*)d_in[5];
    const float* Whh1  = (const float*)d_in[6];
    const float* bih1  = (const float*)d_in[7];
    const float* bhh1  = (const float*)d_in[8];
    const float* Wcls  = (const float*)d_in[9];
    const float* bcls  = (const float*)d_in[10];
    const float* dropu = (const float*)d_in[11];
    float* out = (float*)d_out;

    init_states<<<(BATCH * HID + 255) / 256, 256>>>();
    xproj_kernel<<<dim3(G4 / 64, (STEPS * BATCH) / 64), 256>>>(xs, Wih0, bih0, bhh0);
    for (int t = 0; t < STEPS; ++t) {
        layer0_step<<<HID / 8, 256>>>(Whh0, t);
        layer1_step<<<HID / 8, 256>>>(Wih1, Whh1, bih1, bhh1, t);
    }
    classifier_kernel<<<4000, 256>>>(Wcls, bcls, dropu, out);
}

// round 3
// speedup vs baseline: 1.9104x; 1.9104x over previous
#include <cuda_runtime.h>
#include <cuda_fp16.h>

#define BATCH 128
#define DIN   512
#define HID   1024
#define G4    4096
#define STEPS 64
#define TOFF  55   // (128 - 64 - 9)

typedef unsigned int u32;

// ---------------- device scratch (no allocations allowed) -----------------
__device__ float  g_xproj[(size_t)STEPS * BATCH * G4];     // 128MB fp32
__device__ __half g_h0hi[2][BATCH * HID], g_h0lo[2][BATCH * HID];
__device__ __half g_h1hi[2][BATCH * HID], g_h1lo[2][BATCH * HID];
__device__ float  g_c0[BATCH * HID], g_c1[BATCH * HID];
// Packed weights, fragment-linear: [(ntile*Kt + ktile)*32 + lane] -> {b0hi,b1hi,b0lo,b1lo}
__device__ uint4  g_whh0p[(size_t)512 * 64 * 32];   // 16MB
__device__ uint4  g_wih1p[(size_t)512 * 64 * 32];   // 16MB
__device__ uint4  g_whh1p[(size_t)512 * 64 * 32];   // 16MB
__device__ uint4  g_wih0p[(size_t)512 * 32 * 32];   // 8MB

__device__ __forceinline__ float sigm(float x) { return 1.0f / (1.0f + expf(-x)); }
__device__ __forceinline__ u32 h2u(__half2 h) { return *(u32*)&h; }

// mma.sync m16n8k16 fp16 in / fp32 accum (sm_80+, compiles on base sm_103 PTX)
__device__ __forceinline__ void mma_f16(float* d, const u32* a, const u32* b) {
    asm volatile("mma.sync.aligned.m16n8k16.row.col.f32.f16.f16.f32 "
        "{%0,%1,%2,%3},{%4,%5,%6,%7},{%8,%9},{%0,%1,%2,%3};"
        : "+f"(d[0]), "+f"(d[1]), "+f"(d[2]), "+f"(d[3])
        : "r"(a[0]), "r"(a[1]), "r"(a[2]), "r"(a[3]), "r"(b[0]), "r"(b[1]));
}

// ---------------- init states ----------------------------------------------
__global__ void init_states() {
    int i = blockIdx.x * blockDim.x + threadIdx.x;
    if (i < BATCH * HID) {
        g_h0hi[0][i] = __float2half(0.f); g_h0lo[0][i] = __float2half(0.f);
        g_h1hi[0][i] = __float2half(0.f); g_h1lo[0][i] = __float2half(0.f);
        g_c0[i] = 0.f; g_c1[i] = 0.f;
    }
}

// ---------------- weight packer (runs once per launch) ---------------------
// idx -> (ntile, ktile, lane). n = nt*8 + lane/4; k0 = kt*16 + (lane%4)*2.
// b0 = {W[n][k0], W[n][k0+1]}, b1 = {W[n][k0+8], W[n][k0+9]} ; hi/lo split.
__global__ void pack_w(const float* __restrict__ W, uint4* __restrict__ dst, int Kt) {
    int idx = blockIdx.x * 256 + threadIdx.x;
    int lane = idx & 31;
    int rest = idx >> 5;
    int kt = rest % Kt, nt = rest / Kt;
    int K = Kt * 16;
    int n = nt * 8 + (lane >> 2);
    int k0 = kt * 16 + (lane & 3) * 2;
    const float* wr = W + (size_t)n * K + k0;
    float w00 = wr[0], w01 = wr[1], w10 = wr[8], w11 = wr[9];
    __half h00 = __float2half_rn(w00), h01 = __float2half_rn(w01);
    __half h10 = __float2half_rn(w10), h11 = __float2half_rn(w11);
    __half l00 = __float2half_rn(w00 - __half2float(h00));
    __half l01 = __float2half_rn(w01 - __half2float(h01));
    __half l10 = __float2half_rn(w10 - __half2float(h10));
    __half l11 = __float2half_rn(w11 - __half2float(h11));
    uint4 v;
    v.x = h2u(__halves2half2(h00, h01));
    v.y = h2u(__halves2half2(h10, h11));
    v.z = h2u(__halves2half2(l00, l01));
    v.w = h2u(__halves2half2(l10, l11));
    dst[idx] = v;
}

// ===========================================================================
// Recurrent step kernels. CTA: all 128 batch rows x 32 gate-cols (8 units x
// 4 gates; col j = gate*8 + u). 128 threads = 4 warps; warp w owns rows
// 32w..32w+31 (mtiles 2w, 2w+1). Double-buffered smem, fp16x3 mma.
// ===========================================================================
#define STEP_COMPUTE(NTILES)                                                     \
    {                                                                            \
        _Pragma("unroll")                                                        \
        for (int mtl = 0; mtl < 2; mtl++) {                                      \
            const int r = ((w * 2 + mtl) << 4) + qr;                             \
            u32 ah[4], al[4];                                                    \
            ah[0] = *(const u32*)&sAhi[s][r][qc * 2];                            \
            ah[1] = *(const u32*)&sAhi[s][r + 8][qc * 2];                        \
            ah[2] = *(const u32*)&sAhi[s][r][qc * 2 + 8];                        \
            ah[3] = *(const u32*)&sAhi[s][r + 8][qc * 2 + 8];                    \
            al[0] = *(const u32*)&sAlo[s][r][qc * 2];                            \
            al[1] = *(const u32*)&sAlo[s][r + 8][qc * 2];                        \
            al[2] = *(const u32*)&sAlo[s][r][qc * 2 + 8];                        \
            al[3] = *(const u32*)&sAlo[s][r + 8][qc * 2 + 8];                    \
            _Pragma("unroll")                                                    \
            for (int nt = 0; nt < NTILES; nt++) {                                \
                uint4 bp = sB[s][nt][lane];                                      \
                u32 bh[2] = {bp.x, bp.y}, bl2[2] = {bp.z, bp.w};                 \
                mma_f16(acc[mtl][nt], ah, bh);                                   \
                mma_f16(acc[mtl][nt], al, bh);                                   \
                mma_f16(acc[mtl][nt], ah, bl2);                                  \
            }                                                                    \
        }                                                                        \
    }

__global__ void __launch_bounds__(128) layer0_step(int t) {
    __shared__ __align__(16) __half sAhi[2][128][24];
    __shared__ __align__(16) __half sAlo[2][128][24];
    __shared__ uint4 sB[2][4][32];
    const int tid = threadIdx.x, bx = blockIdx.x;
    const int w = tid >> 5, lane = tid & 31, qr = lane >> 2, qc = lane & 3;
    const int ntb = tid >> 5;                 // staging B ntile
    const __half* Ah = g_h0hi[t & 1];
    const __half* Al = g_h0lo[t & 1];

    float acc[2][4][4];
#pragma unroll
    for (int i = 0; i < 2; i++)
#pragma unroll
        for (int j = 0; j < 4; j++)
#pragma unroll
            for (int k = 0; k < 4; k++) acc[i][j][k] = 0.f;

    uint4 rh0, rh1, rl0, rl1, rb;
    auto ld = [&](int kt) {
        const uint4* pa = (const uint4*)(Ah + (size_t)tid * HID + kt * 16);
        rh0 = pa[0]; rh1 = pa[1];
        const uint4* pl = (const uint4*)(Al + (size_t)tid * HID + kt * 16);
        rl0 = pl[0]; rl1 = pl[1];
        rb = g_whh0p[((size_t)(ntb * 128 + bx) * 64 + kt) * 32 + lane];
    };
    ld(0);
#pragma unroll 1
    for (int kt = 0; kt < 64; kt++) {
        int s = kt & 1;
        uint4* dh = (uint4*)&sAhi[s][tid][0]; dh[0] = rh0; dh[1] = rh1;
        uint4* dl = (uint4*)&sAlo[s][tid][0]; dl[0] = rl0; dl[1] = rl1;
        sB[s][ntb][lane] = rb;
        __syncthreads();
        if (kt + 1 < 64) ld(kt + 1);
        STEP_COMPUTE(4)
        __syncthreads();
    }

    // fused LSTM cell epilogue (thread-local across gates)
    const float* xp = g_xproj + (size_t)t * BATCH * G4;
    __half* Hhi = g_h0hi[(t + 1) & 1];
    __half* Hlo = g_h0lo[(t + 1) & 1];
#pragma unroll
    for (int mtl = 0; mtl < 2; mtl++) {
#pragma unroll
        for (int reg = 0; reg < 4; reg++) {
            int m = (w * 2 + mtl) * 16 + qr + ((reg >= 2) ? 8 : 0);
            int u = qc * 2 + (reg & 1);
            int n = bx * 8 + u;
            const float* xr = xp + (size_t)m * G4 + n;
            float iv = acc[mtl][0][reg] + xr[0];
            float fv = acc[mtl][1][reg] + xr[1024];
            float gv = acc[mtl][2][reg] + xr[2048];
            float ov = acc[mtl][3][reg] + xr[3072];
            int idx = m * HID + n;
            float cn = sigm(fv) * g_c0[idx] + sigm(iv) * tanhf(gv);
            g_c0[idx] = cn;
            float h = sigm(ov) * tanhf(cn);
            __half hh = __float2half_rn(h);
            Hhi[idx] = hh;
            Hlo[idx] = __float2half_rn(h - __half2float(hh));
        }
    }
}

__global__ void __launch_bounds__(128) layer1_step(
    const float* __restrict__ bih1, const float* __restrict__ bhh1, int t)
{
    __shared__ __align__(16) __half sAhi[2][128][24];
    __shared__ __align__(16) __half sAlo[2][128][24];
    __shared__ uint4 sB[2][4][32];
    const int tid = threadIdx.x, bx = blockIdx.x;
    const int w = tid >> 5, lane = tid & 31, qr = lane >> 2, qc = lane & 3;
    const int ntb = tid >> 5;
    const __half* Ah0 = g_h0hi[(t + 1) & 1];
    const __half* Al0 = g_h0lo[(t + 1) & 1];
    const __half* Ah1 = g_h1hi[t & 1];
    const __half* Al1 = g_h1lo[t & 1];

    float acc[2][4][4];
#pragma unroll
    for (int i = 0; i < 2; i++)
#pragma unroll
        for (int j = 0; j < 4; j++)
#pragma unroll
            for (int k = 0; k < 4; k++) acc[i][j][k] = 0.f;

    uint4 rh0, rh1, rl0, rl1, rb;
    auto ld = [&](int kt) {
        const __half* Ah = (kt < 64) ? Ah0 : Ah1;
        const __half* Al = (kt < 64) ? Al0 : Al1;
        const uint4* Bp = (kt < 64) ? g_wih1p : g_whh1p;
        int kk = kt & 63;
        const uint4* pa = (const uint4*)(Ah + (size_t)tid * HID + kk * 16);
        rh0 = pa[0]; rh1 = pa[1];
        const uint4* pl = (const uint4*)(Al + (size_t)tid * HID + kk * 16);
        rl0 = pl[0]; rl1 = pl[1];
        rb = Bp[((size_t)(ntb * 128 + bx) * 64 + kk) * 32 + lane];
    };
    ld(0);
#pragma unroll 1
    for (int kt = 0; kt < 128; kt++) {
        int s = kt & 1;
        uint4* dh = (uint4*)&sAhi[s][tid][0]; dh[0] = rh0; dh[1] = rh1;
        uint4* dl = (uint4*)&sAlo[s][tid][0]; dl[0] = rl0; dl[1] = rl1;
        sB[s][ntb][lane] = rb;
        __syncthreads();
        if (kt + 1 < 128) ld(kt + 1);
        STEP_COMPUTE(4)
        __syncthreads();
    }

    __half* Hhi = g_h1hi[(t + 1) & 1];
    __half* Hlo = g_h1lo[(t + 1) & 1];
#pragma unroll
    for (int mtl = 0; mtl < 2; mtl++) {
#pragma unroll
        for (int reg = 0; reg < 4; reg++) {
            int m = (w * 2 + mtl) * 16 + qr + ((reg >= 2) ? 8 : 0);
            int u = qc * 2 + (reg & 1);
            int n = bx * 8 + u;
            float iv = acc[mtl][0][reg] + bih1[n]        + bhh1[n];
            float fv = acc[mtl][1][reg] + bih1[1024 + n] + bhh1[1024 + n];
            float gv = acc[mtl][2][reg] + bih1[2048 + n] + bhh1[2048 + n];
            float ov = acc[mtl][3][reg] + bih1[3072 + n] + bhh1[3072 + n];
            int idx = m * HID + n;
            float cn = sigm(fv) * g_c1[idx] + sigm(iv) * tanhf(gv);
            g_c1[idx] = cn;
            float h = sigm(ov) * tanhf(cn);
            __half hh = __float2half_rn(h);
            Hhi[idx] = hh;
            Hlo[idx] = __float2half_rn(h - __half2float(hh));
        }
    }
}

// ===========================================================================
// xproj: D[8192,4096] = seq @ W_ih0^T + (bih0+bhh0). CTA: 128 rows x 64 cols,
// 128 threads, warp tile 32x64 (2 mtiles x 8 ntiles). fp32 xs split on the fly.
// row r = t*128 + b  (so staging thread t=b, time=blockIdx.y).
// ===========================================================================
__global__ void __launch_bounds__(128) xproj_kernel(
    const float* __restrict__ xs,
    const float* __restrict__ bih0, const float* __restrict__ bhh0)
{
    __shared__ __align__(16) __half sAhi[2][128][24];
    __shared__ __align__(16) __half sAlo[2][128][24];
    __shared__ uint4 sB[2][8][32];
    const int tid = threadIdx.x;
    const int nbx = blockIdx.x;          // col block (64 cols)
    const int mb  = blockIdx.y;          // time index (128 rows)
    const int w = tid >> 5, lane = tid & 31, qr = lane >> 2, qc = lane & 3;

    float acc[2][8][4];
#pragma unroll
    for (int i = 0; i < 2; i++)
#pragma unroll
        for (int j = 0; j < 8; j++)
#pragma unroll
            for (int k = 0; k < 4; k++) acc[i][j][k] = 0.f;

    const float* arow = xs + (size_t)(tid * 128 + TOFF + mb) * DIN;

    float4 rf[4];
    uint4 rb0, rb1;
    auto ld = [&](int kt) {
#pragma unroll
        for (int i = 0; i < 4; i++)
            rf[i] = *(const float4*)(arow + kt * 16 + i * 4);
        int nt0 = tid >> 5;
        rb0 = g_wih0p[((size_t)(nbx * 8 + nt0) * 32 + kt) * 32 + lane];
        rb1 = g_wih0p[((size_t)(nbx * 8 + 4 + nt0) * 32 + kt) * 32 + lane];
    };
    ld(0);
#pragma unroll 1
    for (int kt = 0; kt < 32; kt++) {
        int s = kt & 1;
        // split fp32 -> hi/lo fp16 pairs and stage
        __half2* dh = (__half2*)&sAhi[s][tid][0];
        __half2* dl = (__half2*)&sAlo[s][tid][0];
#pragma unroll
        for (int i = 0; i < 4; i++) {
            float v[4] = {rf[i].x, rf[i].y, rf[i].z, rf[i].w};
#pragma unroll
            for (int p = 0; p < 2; p++) {
                float x0 = v[p * 2], x1 = v[p * 2 + 1];
                __half a0 = __float2half_rn(x0), a1 = __float2half_rn(x1);
                dh[i * 2 + p] = __halves2half2(a0, a1);
                dl[i * 2 + p] = __halves2half2(
                    __float2half_rn(x0 - __half2float(a0)),
                    __float2half_rn(x1 - __half2float(a1)));
            }
        }
        int nt0 = tid >> 5;
        sB[s][nt0][lane] = rb0;
        sB[s][4 + nt0][lane] = rb1;
        __syncthreads();
        if (kt + 1 < 32) ld(kt + 1);
        STEP_COMPUTE(8)
        __syncthreads();
    }

    // epilogue: D + biases -> g_xproj fp32
#pragma unroll
    for (int mtl = 0; mtl < 2; mtl++) {
        int m0 = mb * 128 + (w * 2 + mtl) * 16 + qr;
#pragma unroll
        for (int nt = 0; nt < 8; nt++) {
            int colb = nbx * 64 + nt * 8 + qc * 2;
            float b0v = bih0[colb] + bhh0[colb];
            float b1v = bih0[colb + 1] + bhh0[colb + 1];
            float2 v0 = make_float2(acc[mtl][nt][0] + b0v, acc[mtl][nt][1] + b1v);
            float2 v1 = make_float2(acc[mtl][nt][2] + b0v, acc[mtl][nt][3] + b1v);
            *(float2*)&g_xproj[(size_t)m0 * G4 + colb] = v0;
            *(float2*)&g_xproj[(size_t)(m0 + 8) * G4 + colb] = v1;
        }
    }
}

// ---------------- classifier: out = (h1 * keep * 2) @ Wcls^T + bcls --------
__global__ void __launch_bounds__(256) classifier_kernel(
    const float* __restrict__ Wcls, const float* __restrict__ bcls,
    const float* __restrict__ dropu, float* __restrict__ out)
{
    int gw = (blockIdx.x * blockDim.x + threadIdx.x) >> 5;
    int lane = threadIdx.x & 31;
    int j = gw >> 5;            // class 0..999
    int b0 = (gw & 31) * 4;
    const __half* hi = g_h1hi[0];   // t=63 -> buffer 0
    const __half* lo = g_h1lo[0];

    float acc[4] = {0.f, 0.f, 0.f, 0.f};
#pragma unroll
    for (int it = 0; it < 8; ++it) {
        int h = it * 128 + lane * 4;
        float4 wv = *(const float4*)&Wcls[(size_t)j * HID + h];
#pragma unroll
        for (int bi = 0; bi < 4; ++bi) {
            int b = b0 + bi;
            int idx = b * HID + h;
            __half2 a0 = *(const __half2*)&hi[idx];
            __half2 a1 = *(const __half2*)&hi[idx + 2];
            __half2 c0 = *(const __half2*)&lo[idx];
            __half2 c1 = *(const __half2*)&lo[idx + 2];
            float2 f0 = __half22float2(a0), f1 = __half22float2(a1);
            float2 g0 = __half22float2(c0), g1 = __half22float2(c1);
            float x0 = f0.x + g0.x, x1 = f0.y + g0.y;
            float x2 = f1.x + g1.x, x3 = f1.y + g1.y;
            float4 u = *(const float4*)&dropu[(size_t)b * HID + h];
            acc[bi] += (u.x > 0.5f ? x0 : 0.f) * wv.x
                     + (u.y > 0.5f ? x1 : 0.f) * wv.y
                     + (u.z > 0.5f ? x2 : 0.f) * wv.z
                     + (u.w > 0.5f ? x3 : 0.f) * wv.w;
        }
    }
#pragma unroll
    for (int bi = 0; bi < 4; ++bi) {
        float v = acc[bi];
#pragma unroll
        for (int off = 16; off; off >>= 1)
            v += __shfl_xor_sync(0xffffffffu, v, off);
        if (lane == 0)
            out[(size_t)(b0 + bi) * 1000 + j] = 2.0f * v + bcls[j];
    }
}

// ---------------- launch ----------------------------------------------------
extern "C" void kernel_launch(void* const* d_in, const int* in_sizes, int n_in,
                              void* d_out, int out_size)
{
    const float* xs    = (const float*)d_in[0];
    const float* Wih0  = (const float*)d_in[1];
    const float* Whh0  = (const float*)d_in[2];
    const float* bih0  = (const float*)d_in[3];
    const float* bhh0  = (const float*)d_in[4];
    const float* Wih1  = (const float*)d_in[5];
    const float* Whh1  = (const float*)d_in[6];
    const float* bih1  = (const float*)d_in[7];
    const float* bhh1  = (const float*)d_in[8];
    const float* Wcls  = (const float*)d_in[9];
    const float* bcls  = (const float*)d_in[10];
    const float* dropu = (const float*)d_in[11];
    float* out = (float*)d_out;

    uint4* whh0p; cudaGetSymbolAddress((void**)&whh0p, g_whh0p);
    uint4* wih1p; cudaGetSymbolAddress((void**)&wih1p, g_wih1p);
    uint4* whh1p; cudaGetSymbolAddress((void**)&whh1p, g_whh1p);
    uint4* wih0p; cudaGetSymbolAddress((void**)&wih0p, g_wih0p);

    init_states<<<(BATCH * HID + 255) / 256, 256>>>();
    pack_w<<<4096, 256>>>(Whh0, whh0p, 64);
    pack_w<<<4096, 256>>>(Wih1, wih1p, 64);
    pack_w<<<4096, 256>>>(Whh1, whh1p, 64);
    pack_w<<<2048, 256>>>(Wih0, wih0p, 32);

    xproj_kernel<<<dim3(G4 / 64, STEPS), 128>>>(xs, bih0, bhh0);

    for (int t = 0; t < STEPS; ++t) {
        layer0_step<<<128, 128>>>(t);
        layer1_step<<<128, 128>>>(bih1, bhh1, t);
    }
    classifier_kernel<<<4000, 256>>>(Wcls, bcls, dropu, out);
}

// round 4
// speedup vs baseline: 3.6405x; 1.9057x over previous
#include <cuda_runtime.h>
#include <cuda_fp16.h>

#define BATCH 128
#define DIN   512
#define HID   1024
#define G4    4096
#define STEPS 64
#define TOFF  55   // (128 - 64 - 9)

typedef unsigned int u32;
typedef unsigned long long u64;

// ---------------- device scratch (no allocations allowed) -----------------
__device__ float  g_xproj[(size_t)STEPS * BATCH * G4];     // 128MB fp32
__device__ __half g_h0hi[2][BATCH * HID], g_h0lo[2][BATCH * HID];
__device__ __half g_h1hi[2][BATCH * HID], g_h1lo[2][BATCH * HID];
__device__ float  g_c0[BATCH * HID], g_c1[BATCH * HID];
// Packed weights, fragment-linear: [(ntile*Kt + kt16)*32 + lane] -> {b0hi,b1hi,b0lo,b1lo}
__device__ uint4  g_whh0p[(size_t)512 * 64 * 32];
__device__ uint4  g_wih1p[(size_t)512 * 64 * 32];
__device__ uint4  g_whh1p[(size_t)512 * 64 * 32];
__device__ uint4  g_wih0p[(size_t)512 * 32 * 32];

__device__ __forceinline__ float sigm(float x) { return 1.0f / (1.0f + expf(-x)); }
__device__ __forceinline__ u32 h2u(__half2 h) { return *(u32*)&h; }

__device__ __forceinline__ void mma_f16(float* d, const u32* a, const u32* b) {
    asm volatile("mma.sync.aligned.m16n8k16.row.col.f32.f16.f16.f32 "
        "{%0,%1,%2,%3},{%4,%5,%6,%7},{%8,%9},{%0,%1,%2,%3};"
        : "+f"(d[0]), "+f"(d[1]), "+f"(d[2]), "+f"(d[3])
        : "r"(a[0]), "r"(a[1]), "r"(a[2]), "r"(a[3]), "r"(b[0]), "r"(b[1]));
}
__device__ __forceinline__ u32 smem_u32(const void* p) {
    u32 a;
    asm("{ .reg .u64 t; cvta.to.shared.u64 t, %1; cvt.u32.u64 %0, t; }" : "=r"(a) : "l"(p));
    return a;
}
__device__ __forceinline__ void cpa16(u32 dst, const void* src) {
    asm volatile("cp.async.cg.shared.global [%0], [%1], 16;"
                 :: "r"(dst), "l"(__cvta_generic_to_global(src)) : "memory");
}
__device__ __forceinline__ void cpa_commit() {
    asm volatile("cp.async.commit_group;" ::: "memory");
}
template<int N> __device__ __forceinline__ void cpa_wait() {
    asm volatile("cp.async.wait_group %0;" :: "n"(N) : "memory");
}
__device__ __forceinline__ void ldm4(u32* r, u32 addr) {
    asm volatile("ldmatrix.sync.aligned.m8n8.x4.shared.b16 {%0,%1,%2,%3}, [%4];"
        : "=r"(r[0]), "=r"(r[1]), "=r"(r[2]), "=r"(r[3]) : "r"(addr));
}

// smem layout (dynamic, 86016 B):
//  AHI: stage s at s*10240          (128 rows x 64B data, 80B stride)
//  ALO: 30720 + s*10240
//  B:   61440 + s*8192              ([mat(2)][ (nt*2+j)*32+lane ] uint4)
#define SM_ALO   30720
#define SM_B     61440
#define SM_TOTAL 86016

// ---------------- init states ----------------------------------------------
__global__ void init_states() {
    int i = blockIdx.x * blockDim.x + threadIdx.x;
    if (i < BATCH * HID) {
        __half z = __float2half(0.f);
        g_h0hi[0][i] = z; g_h0lo[0][i] = z; g_h0hi[1][i] = z; g_h0lo[1][i] = z;
        g_h1hi[0][i] = z; g_h1lo[0][i] = z; g_h1hi[1][i] = z; g_h1lo[1][i] = z;
        g_c0[i] = 0.f; g_c1[i] = 0.f;
    }
}

// ---------------- weight packer (unchanged, validated) ---------------------
__global__ void pack_w(const float* __restrict__ W, uint4* __restrict__ dst, int Kt) {
    int idx = blockIdx.x * 256 + threadIdx.x;
    int lane = idx & 31;
    int rest = idx >> 5;
    int kt = rest % Kt, nt = rest / Kt;
    int K = Kt * 16;
    int n = nt * 8 + (lane >> 2);
    int k0 = kt * 16 + (lane & 3) * 2;
    const float* wr = W + (size_t)n * K + k0;
    float w00 = wr[0], w01 = wr[1], w10 = wr[8], w11 = wr[9];
    __half h00 = __float2half_rn(w00), h01 = __float2half_rn(w01);
    __half h10 = __float2half_rn(w10), h11 = __float2half_rn(w11);
    uint4 v;
    v.x = h2u(__halves2half2(h00, h01));
    v.y = h2u(__halves2half2(h10, h11));
    v.z = h2u(__halves2half2(__float2half_rn(w00 - __half2float(h00)),
                             __float2half_rn(w01 - __half2float(h01))));
    v.w = h2u(__halves2half2(__float2half_rn(w10 - __half2float(h10)),
                             __float2half_rn(w11 - __half2float(h11))));
    dst[idx] = v;
}

// ---------------- L0(0): h0=0 -> pure elementwise cell on xproj[0] ---------
__global__ void l0_first() {
    int i = blockIdx.x * 256 + threadIdx.x;
    if (i >= BATCH * HID) return;
    int m = i >> 10, n = i & 1023;
    const float* xr = g_xproj + (size_t)m * G4;
    float iv = xr[n], gv = xr[2048 + n], ov = xr[3072 + n];
    float cn = sigm(iv) * tanhf(gv);
    g_c0[i] = cn;
    float h = sigm(ov) * tanhf(cn);
    __half hh = __float2half_rn(h);
    g_h0hi[1][i] = hh;
    g_h0lo[1][i] = __float2half_rn(h - __half2float(hh));
}

// ===========================================================================
// Fused step: computes L1(t) AND (if do_l0) L0(t+1) in one pipeline.
// Grid 128, 256 threads (8 warps; warp w owns rows w*16..w*16+15).
// Phase A (kt 0..31):  A = h0(t+1), B0 = Wih1 -> acc1, B1 = Whh0 -> acc0
// Phase B (kt 32..63): A = h1(t),   B0 = Whh1 -> acc1
// ===========================================================================
__global__ void __launch_bounds__(256) step_pair(
    const float* __restrict__ bih1, const float* __restrict__ bhh1,
    int t, int do_l0)
{
    extern __shared__ char smem[];
    const int tid = threadIdx.x, bx = blockIdx.x;
    const int w = tid >> 5, lane = tid & 31, qr = lane >> 2, qc = lane & 3;
    const u32 sb = smem_u32(smem);

    const __half* AhA = g_h0hi[(t + 1) & 1];
    const __half* AlA = g_h0lo[(t + 1) & 1];
    const __half* AhB = g_h1hi[t & 1];
    const __half* AlB = g_h1lo[t & 1];

    float acc1[4][4], acc0[4][4];
#pragma unroll
    for (int i = 0; i < 4; i++)
#pragma unroll
        for (int j = 0; j < 4; j++) { acc1[i][j] = 0.f; acc0[i][j] = 0.f; }

    // per-thread invariant staging coords
    const int rowA = tid >> 1;                 // A row (0..127)
    const int cA   = (tid & 1) * 2;            // chunk 0/2 (two 16B chunks = 32B)
    const size_t gA = (size_t)rowA * HID + cA * 8;
    const u32  dA   = sb + rowA * 80 + cA * 16;
    const int ntB = tid >> 6, jB = (tid >> 5) & 1, lnB = tid & 31;
    const size_t bBase = ((size_t)(ntB * 128 + bx) * 64 + jB) * 32 + lnB;
    const u32  dB   = sb + SM_B + (((ntB * 2 + jB) * 32 + lnB) << 4);

    auto issue = [&](int kt) {
        int s = kt % 3;
        bool pa = kt < 32;
        int kk = pa ? kt : kt - 32;
        const __half* Ah = pa ? AhA : AhB;
        const __half* Al = pa ? AlA : AlB;
        size_t ga = gA + kk * 32;
        u32 da = dA + s * 10240;
        cpa16(da,              Ah + ga);
        cpa16(da + 16,         Ah + ga + 8);
        cpa16(da + SM_ALO,     Al + ga);
        cpa16(da + SM_ALO + 16, Al + ga + 8);
        size_t bs = bBase + (size_t)kk * 64;
        u32 db = dB + s * 8192;
        if (pa) {
            cpa16(db, g_wih1p + bs);
            if (do_l0) cpa16(db + 4096, g_whh0p + bs);
        } else {
            cpa16(db, g_whh1p + bs);
        }
    };

    issue(0); cpa_commit();
    issue(1); cpa_commit();

    const u32 aFrag = sb + (w * 16 + (lane & 15)) * 80 + ((lane >> 4) * 16);

#pragma unroll 1
    for (int kt = 0; kt < 64; kt++) {
        int s = kt % 3;
        cpa_wait<1>();
        __syncthreads();
        if (kt + 2 < 64) issue(kt + 2);
        cpa_commit();
        bool pa = kt < 32;
        const uint4* bst = (const uint4*)(smem + SM_B + s * 8192);
#pragma unroll
        for (int sub = 0; sub < 2; sub++) {
            u32 ah[4], al[4];
            ldm4(ah, aFrag + s * 10240 + sub * 32);
            ldm4(al, aFrag + s * 10240 + SM_ALO + sub * 32);
#pragma unroll
            for (int nt = 0; nt < 4; nt++) {
                uint4 bp = bst[(nt * 2 + sub) * 32 + lane];
                u32 bh[2] = {bp.x, bp.y}, bl[2] = {bp.z, bp.w};
                mma_f16(acc1[nt], ah, bh);
                mma_f16(acc1[nt], al, bh);
                mma_f16(acc1[nt], ah, bl);
            }
            if (pa && do_l0) {
#pragma unroll
                for (int nt = 0; nt < 4; nt++) {
                    uint4 bp = bst[256 + (nt * 2 + sub) * 32 + lane];
                    u32 bh[2] = {bp.x, bp.y}, bl[2] = {bp.z, bp.w};
                    mma_f16(acc0[nt], ah, bh);
                    mma_f16(acc0[nt], al, bh);
                    mma_f16(acc0[nt], ah, bl);
                }
            }
        }
    }
    cpa_wait<0>();

    // ---- L1(t) epilogue ----
    {
        __half* Hhi = g_h1hi[(t + 1) & 1];
        __half* Hlo = g_h1lo[(t + 1) & 1];
#pragma unroll
        for (int rr = 0; rr < 2; rr++) {
#pragma unroll
            for (int e = 0; e < 2; e++) {
                int m = w * 16 + qr + rr * 8;
                int n = bx * 8 + qc * 2 + e;
                int ri = rr * 2 + e;
                float iv = acc1[0][ri] + bih1[n]        + bhh1[n];
                float fv = acc1[1][ri] + bih1[1024 + n] + bhh1[1024 + n];
                float gv = acc1[2][ri] + bih1[2048 + n] + bhh1[2048 + n];
                float ov = acc1[3][ri] + bih1[3072 + n] + bhh1[3072 + n];
                int idx = m * HID + n;
                float cn = sigm(fv) * g_c1[idx] + sigm(iv) * tanhf(gv);
                g_c1[idx] = cn;
                float h = sigm(ov) * tanhf(cn);
                __half hh = __float2half_rn(h);
                Hhi[idx] = hh;
                Hlo[idx] = __float2half_rn(h - __half2float(hh));
            }
        }
    }
    // ---- L0(t+1) epilogue: writes state(t+2) into buffer (t+2)&1 == t&1 ----
    if (do_l0) {
        const float* xp = g_xproj + (size_t)(t + 1) * BATCH * G4;
        __half* Hhi = g_h0hi[t & 1];
        __half* Hlo = g_h0lo[t & 1];
#pragma unroll
        for (int rr = 0; rr < 2; rr++) {
#pragma unroll
            for (int e = 0; e < 2; e++) {
                int m = w * 16 + qr + rr * 8;
                int n = bx * 8 + qc * 2 + e;
                int ri = rr * 2 + e;
                const float* xr = xp + (size_t)m * G4 + n;
                float iv = acc0[0][ri] + xr[0];
                float fv = acc0[1][ri] + xr[1024];
                float gv = acc0[2][ri] + xr[2048];
                float ov = acc0[3][ri] + xr[3072];
                int idx = m * HID + n;
                float cn = sigm(fv) * g_c0[idx] + sigm(iv) * tanhf(gv);
                g_c0[idx] = cn;
                float h = sigm(ov) * tanhf(cn);
                __half hh = __float2half_rn(h);
                Hhi[idx] = hh;
                Hlo[idx] = __float2half_rn(h - __half2float(hh));
            }
        }
    }
}

// ===========================================================================
// xproj (round-3 validated kernel, unchanged)
// ===========================================================================
#define STEP_COMPUTE(NTILES)                                                     \
    {                                                                            \
        _Pragma("unroll")                                                        \
        for (int mtl = 0; mtl < 2; mtl++) {                                      \
            const int r = ((w * 2 + mtl) << 4) + qr;                             \
            u32 ah[4], al[4];                                                    \
            ah[0] = *(const u32*)&sAhi[s][r][qc * 2];                            \
            ah[1] = *(const u32*)&sAhi[s][r + 8][qc * 2];                        \
            ah[2] = *(const u32*)&sAhi[s][r][qc * 2 + 8];                        \
            ah[3] = *(const u32*)&sAhi[s][r + 8][qc * 2 + 8];                    \
            al[0] = *(const u32*)&sAlo[s][r][qc * 2];                            \
            al[1] = *(const u32*)&sAlo[s][r + 8][qc * 2];                        \
            al[2] = *(const u32*)&sAlo[s][r][qc * 2 + 8];                        \
            al[3] = *(const u32*)&sAlo[s][r + 8][qc * 2 + 8];                    \
            _Pragma("unroll")                                                    \
            for (int nt = 0; nt < NTILES; nt++) {                                \
                uint4 bp = sB[s][nt][lane];                                      \
                u32 bh[2] = {bp.x, bp.y}, bl2[2] = {bp.z, bp.w};                 \
                mma_f16(acc[mtl][nt], ah, bh);                                   \
                mma_f16(acc[mtl][nt], al, bh);                                   \
                mma_f16(acc[mtl][nt], ah, bl2);                                  \
            }                                                                    \
        }                                                                        \
    }

__global__ void __launch_bounds__(128) xproj_kernel(
    const float* __restrict__ xs,
    const float* __restrict__ bih0, const float* __restrict__ bhh0)
{
    __shared__ __align__(16) __half sAhi[2][128][24];
    __shared__ __align__(16) __half sAlo[2][128][24];
    __shared__ uint4 sB[2][8][32];
    const int tid = threadIdx.x;
    const int nbx = blockIdx.x;
    const int mb  = blockIdx.y;
    const int w = tid >> 5, lane = tid & 31, qr = lane >> 2, qc = lane & 3;

    float acc[2][8][4];
#pragma unroll
    for (int i = 0; i < 2; i++)
#pragma unroll
        for (int j = 0; j < 8; j++)
#pragma unroll
            for (int k = 0; k < 4; k++) acc[i][j][k] = 0.f;

    const float* arow = xs + (size_t)(tid * 128 + TOFF + mb) * DIN;

    float4 rf[4];
    uint4 rb0, rb1;
    auto ld = [&](int kt) {
#pragma unroll
        for (int i = 0; i < 4; i++)
            rf[i] = *(const float4*)(arow + kt * 16 + i * 4);
        int nt0 = tid >> 5;
        rb0 = g_wih0p[((size_t)(nbx * 8 + nt0) * 32 + kt) * 32 + lane];
        rb1 = g_wih0p[((size_t)(nbx * 8 + 4 + nt0) * 32 + kt) * 32 + lane];
    };
    ld(0);
#pragma unroll 1
    for (int kt = 0; kt < 32; kt++) {
        int s = kt & 1;
        __half2* dh = (__half2*)&sAhi[s][tid][0];
        __half2* dl = (__half2*)&sAlo[s][tid][0];
#pragma unroll
        for (int i = 0; i < 4; i++) {
            float v[4] = {rf[i].x, rf[i].y, rf[i].z, rf[i].w};
#pragma unroll
            for (int p = 0; p < 2; p++) {
                float x0 = v[p * 2], x1 = v[p * 2 + 1];
                __half a0 = __float2half_rn(x0), a1 = __float2half_rn(x1);
                dh[i * 2 + p] = __halves2half2(a0, a1);
                dl[i * 2 + p] = __halves2half2(
                    __float2half_rn(x0 - __half2float(a0)),
                    __float2half_rn(x1 - __half2float(a1)));
            }
        }
        int nt0 = tid >> 5;
        sB[s][nt0][lane] = rb0;
        sB[s][4 + nt0][lane] = rb1;
        __syncthreads();
        if (kt + 1 < 32) ld(kt + 1);
        STEP_COMPUTE(8)
        __syncthreads();
    }

#pragma unroll
    for (int mtl = 0; mtl < 2; mtl++) {
        int m0 = mb * 128 + (w * 2 + mtl) * 16 + qr;
#pragma unroll
        for (int nt = 0; nt < 8; nt++) {
            int colb = nbx * 64 + nt * 8 + qc * 2;
            float b0v = bih0[colb] + bhh0[colb];
            float b1v = bih0[colb + 1] + bhh0[colb + 1];
            float2 v0 = make_float2(acc[mtl][nt][0] + b0v, acc[mtl][nt][1] + b1v);
            float2 v1 = make_float2(acc[mtl][nt][2] + b0v, acc[mtl][nt][3] + b1v);
            *(float2*)&g_xproj[(size_t)m0 * G4 + colb] = v0;
            *(float2*)&g_xproj[(size_t)(m0 + 8) * G4 + colb] = v1;
        }
    }
}

// ---------------- classifier (unchanged) ------------------------------------
__global__ void __launch_bounds__(256) classifier_kernel(
    const float* __restrict__ Wcls, const float* __restrict__ bcls,
    const float* __restrict__ dropu, float* __restrict__ out)
{
    int gw = (blockIdx.x * blockDim.x + threadIdx.x) >> 5;
    int lane = threadIdx.x & 31;
    int j = gw >> 5;
    int b0 = (gw & 31) * 4;
    const __half* hi = g_h1hi[0];
    const __half* lo = g_h1lo[0];

    float acc[4] = {0.f, 0.f, 0.f, 0.f};
#pragma unroll
    for (int it = 0; it < 8; ++it) {
        int h = it * 128 + lane * 4;
        float4 wv = *(const float4*)&Wcls[(size_t)j * HID + h];
#pragma unroll
        for (int bi = 0; bi < 4; ++bi) {
            int b = b0 + bi;
            int idx = b * HID + h;
            __half2 a0 = *(const __half2*)&hi[idx];
            __half2 a1 = *(const __half2*)&hi[idx + 2];
            __half2 c0 = *(const __half2*)&lo[idx];
            __half2 c1 = *(const __half2*)&lo[idx + 2];
            float2 f0 = __half22float2(a0), f1 = __half22float2(a1);
            float2 g0 = __half22float2(c0), g1 = __half22float2(c1);
            float x0 = f0.x + g0.x, x1 = f0.y + g0.y;
            float x2 = f1.x + g1.x, x3 = f1.y + g1.y;
            float4 u = *(const float4*)&dropu[(size_t)b * HID + h];
            acc[bi] += (u.x > 0.5f ? x0 : 0.f) * wv.x
                     + (u.y > 0.5f ? x1 : 0.f) * wv.y
                     + (u.z > 0.5f ? x2 : 0.f) * wv.z
                     + (u.w > 0.5f ? x3 : 0.f) * wv.w;
        }
    }
#pragma unroll
    for (int bi = 0; bi < 4; ++bi) {
        float v = acc[bi];
#pragma unroll
        for (int off = 16; off; off >>= 1)
            v += __shfl_xor_sync(0xffffffffu, v, off);
        if (lane == 0)
            out[(size_t)(b0 + bi) * 1000 + j] = 2.0f * v + bcls[j];
    }
}

// ---------------- launch ----------------------------------------------------
extern "C" void kernel_launch(void* const* d_in, const int* in_sizes, int n_in,
                              void* d_out, int out_size)
{
    const float* xs    = (const float*)d_in[0];
    const float* Wih0  = (const float*)d_in[1];
    const float* Whh0  = (const float*)d_in[2];
    const float* bih0  = (const float*)d_in[3];
    const float* bhh0  = (const float*)d_in[4];
    const float* Wih1  = (const float*)d_in[5];
    const float* Whh1  = (const float*)d_in[6];
    const float* bih1  = (const float*)d_in[7];
    const float* bhh1  = (const float*)d_in[8];
    const float* Wcls  = (const float*)d_in[9];
    const float* bcls  = (const float*)d_in[10];
    const float* dropu = (const float*)d_in[11];
    float* out = (float*)d_out;

    static int attr_done = 0;
    if (!attr_done) {
        cudaFuncSetAttribute(step_pair, cudaFuncAttributeMaxDynamicSharedMemorySize, SM_TOTAL);
        attr_done = 1;
    }

    uint4* whh0p; cudaGetSymbolAddress((void**)&whh0p, g_whh0p);
    uint4* wih1p; cudaGetSymbolAddress((void**)&wih1p, g_wih1p);
    uint4* whh1p; cudaGetSymbolAddress((void**)&whh1p, g_whh1p);
    uint4* wih0p; cudaGetSymbolAddress((void**)&wih0p, g_wih0p);

    init_states<<<(BATCH * HID + 255) / 256, 256>>>();
    pack_w<<<4096, 256>>>(Whh0, whh0p, 64);
    pack_w<<<4096, 256>>>(Wih1, wih1p, 64);
    pack_w<<<4096, 256>>>(Whh1, whh1p, 64);
    pack_w<<<2048, 256>>>(Wih0, wih0p, 32);

    xproj_kernel<<<dim3(G4 / 64, STEPS), 128>>>(xs, bih0, bhh0);
    l0_first<<<(BATCH * HID + 255) / 256, 256>>>();

    for (int t = 0; t < STEPS - 1; ++t)
        step_pair<<<128, 256, SM_TOTAL>>>(bih1, bhh1, t, 1);
    step_pair<<<128, 256, SM_TOTAL>>>(bih1, bhh1, STEPS - 1, 0);

    classifier_kernel<<<4000, 256>>>(Wcls, bcls, dropu, out);
}

// round 5
// speedup vs baseline: 3.8595x; 1.0602x over previous
#include <cuda_runtime.h>
#include <cuda_fp16.h>

#define BATCH 128
#define DIN   512
#define HID   1024
#define G4    4096
#define STEPS 64
#define TOFF  55   // (128 - 64 - 9)

typedef unsigned int u32;

// ---------------- device scratch (no allocations allowed) -----------------
__device__ float  g_xproj[(size_t)STEPS * BATCH * G4];
__device__ __half g_h0hi[2][BATCH * HID], g_h0lo[2][BATCH * HID];
__device__ __half g_h1hi[2][BATCH * HID], g_h1lo[2][BATCH * HID];
__device__ float  g_c0[BATCH * HID];
__device__ uint4  g_whh0p[(size_t)512 * 64 * 32];
__device__ uint4  g_wih1p[(size_t)512 * 64 * 32];
__device__ uint4  g_whh1p[(size_t)512 * 64 * 32];
__device__ uint4  g_wih0p[(size_t)512 * 32 * 32];
__device__ u32    g_bar_count, g_bar_gen;

__device__ __forceinline__ float sigm(float x) { return 1.0f / (1.0f + expf(-x)); }
__device__ __forceinline__ u32 h2u(__half2 h) { return *(u32*)&h; }

__device__ __forceinline__ void mma_f16(float* d, const u32* a, const u32* b) {
    asm volatile("mma.sync.aligned.m16n8k16.row.col.f32.f16.f16.f32 "
        "{%0,%1,%2,%3},{%4,%5,%6,%7},{%8,%9},{%0,%1,%2,%3};"
        : "+f"(d[0]), "+f"(d[1]), "+f"(d[2]), "+f"(d[3])
        : "r"(a[0]), "r"(a[1]), "r"(a[2]), "r"(a[3]), "r"(b[0]), "r"(b[1]));
}
__device__ __forceinline__ u32 smem_u32(const void* p) {
    u32 a;
    asm("{ .reg .u64 t; cvta.to.shared.u64 t, %1; cvt.u32.u64 %0, t; }" : "=r"(a) : "l"(p));
    return a;
}
__device__ __forceinline__ void cpa16(u32 dst, const void* src) {
    asm volatile("cp.async.cg.shared.global [%0], [%1], 16;"
                 :: "r"(dst), "l"(__cvta_generic_to_global(src)) : "memory");
}
__device__ __forceinline__ void cpa_commit() {
    asm volatile("cp.async.commit_group;" ::: "memory");
}
template<int N> __device__ __forceinline__ void cpa_wait() {
    asm volatile("cp.async.wait_group %0;" :: "n"(N) : "memory");
}
__device__ __forceinline__ void ldm4(u32* r, u32 addr) {
    asm volatile("ldmatrix.sync.aligned.m8n8.x4.shared.b16 {%0,%1,%2,%3}, [%4];"
        : "=r"(r[0]), "=r"(r[1]), "=r"(r[2]), "=r"(r[3]) : "r"(addr));
}

// persistent-kernel smem: 4 stages
//  AHI: s*10240 (0..40960)   ALO: 40960 + s*10240   B: 81920 + s*8192
#define PS_ALO   40960
#define PS_B     81920
#define PS_TOTAL 114688

// ---------------- grid-wide software barrier -------------------------------
__device__ __forceinline__ void grid_barrier(int step) {
    __syncthreads();
    if (threadIdx.x == 0) {
        __threadfence();
        u32 prev = atomicAdd(&g_bar_count, 1u);
        if (prev == (u32)(step * 128 + 127)) {
            atomicExch(&g_bar_gen, (u32)(step + 1));
        } else {
            u32 g;
            do {
                __nanosleep(64);
                asm volatile("ld.acquire.gpu.u32 %0, [%1];"
                             : "=r"(g) : "l"((const u32*)&g_bar_gen));
            } while (g <= (u32)step);
        }
    }
    __syncthreads();
}

// ---------------- init states ----------------------------------------------
__global__ void init_states() {
    int i = blockIdx.x * blockDim.x + threadIdx.x;
    if (i == 0) { g_bar_count = 0u; g_bar_gen = 0u; }
    if (i < BATCH * HID) {
        __half z = __float2half(0.f);
        g_h0hi[0][i] = z; g_h0lo[0][i] = z; g_h0hi[1][i] = z; g_h0lo[1][i] = z;
        g_h1hi[0][i] = z; g_h1lo[0][i] = z; g_h1hi[1][i] = z; g_h1lo[1][i] = z;
        g_c0[i] = 0.f;
    }
}

// ---------------- weight packers (2 launches) ------------------------------
__device__ __forceinline__ void pack_one(
    const float* __restrict__ W, uint4* __restrict__ dst, int Kt, int idx)
{
    int lane = idx & 31;
    int rest = idx >> 5;
    int kt = rest % Kt, nt = rest / Kt;
    int K = Kt * 16;
    int n = nt * 8 + (lane >> 2);
    int k0 = kt * 16 + (lane & 3) * 2;
    const float* wr = W + (size_t)n * K + k0;
    float w00 = wr[0], w01 = wr[1], w10 = wr[8], w11 = wr[9];
    __half h00 = __float2half_rn(w00), h01 = __float2half_rn(w01);
    __half h10 = __float2half_rn(w10), h11 = __float2half_rn(w11);
    uint4 v;
    v.x = h2u(__halves2half2(h00, h01));
    v.y = h2u(__halves2half2(h10, h11));
    v.z = h2u(__halves2half2(__float2half_rn(w00 - __half2float(h00)),
                             __float2half_rn(w01 - __half2float(h01))));
    v.w = h2u(__halves2half2(__float2half_rn(w10 - __half2float(h10)),
                             __float2half_rn(w11 - __half2float(h11))));
    dst[idx] = v;
}
#define PACK_N64 (512 * 64 * 32)
#define PACK_N32 (512 * 32 * 32)
__global__ void pack_a(const float* __restrict__ Whh0, const float* __restrict__ Wih1) {
    int idx = blockIdx.x * 256 + threadIdx.x;
    if (idx < PACK_N64) pack_one(Whh0, g_whh0p, 64, idx);
    else                pack_one(Wih1, g_wih1p, 64, idx - PACK_N64);
}
__global__ void pack_b(const float* __restrict__ Whh1, const float* __restrict__ Wih0) {
    int idx = blockIdx.x * 256 + threadIdx.x;
    if (idx < PACK_N64) pack_one(Whh1, g_whh1p, 64, idx);
    else                pack_one(Wih0, g_wih0p, 32, idx - PACK_N64);
}

// ---------------- L0(0): h0=0 -> elementwise cell on xproj[0] ---------------
__global__ void l0_first() {
    int i = blockIdx.x * 256 + threadIdx.x;
    if (i >= BATCH * HID) return;
    int m = i >> 10, n = i & 1023;
    const float* xr = g_xproj + (size_t)m * G4;
    float iv = xr[n], gv = xr[2048 + n], ov = xr[3072 + n];
    float cn = sigm(iv) * tanhf(gv);
    g_c0[i] = cn;
    float h = sigm(ov) * tanhf(cn);
    __half hh = __float2half_rn(h);
    g_h0hi[1][i] = hh;
    g_h0lo[1][i] = __float2half_rn(h - __half2float(hh));
}

// ===========================================================================
// Persistent step kernel: runs all 64 steps. Step t computes L1(t) and
// (t<63) L0(t+1). Grid 128 (co-resident), 256 threads, 4-stage cp.async.
// c-state and L1 biases live in registers for the whole run.
// ===========================================================================
__global__ void __launch_bounds__(256) step_persist(
    const float* __restrict__ bih1, const float* __restrict__ bhh1)
{
    extern __shared__ char smem[];
    const int tid = threadIdx.x, bx = blockIdx.x;
    const int w = tid >> 5, lane = tid & 31, qr = lane >> 2, qc = lane & 3;
    const u32 sb = smem_u32(smem);
    const int n0 = bx * 8 + qc * 2;

    // biases in regs
    float bs[4][2];
#pragma unroll
    for (int g = 0; g < 4; g++) {
        bs[g][0] = bih1[g * 1024 + n0] + bhh1[g * 1024 + n0];
        bs[g][1] = bih1[g * 1024 + n0 + 1] + bhh1[g * 1024 + n0 + 1];
    }
    // c-state in regs (ri = rr*2 + e), rows m = w*16 + qr + rr*8
    float c1r[4] = {0.f, 0.f, 0.f, 0.f};
    float c0r[4];
#pragma unroll
    for (int rr = 0; rr < 2; rr++) {
        int m = w * 16 + qr + rr * 8;
        c0r[rr * 2 + 0] = g_c0[m * HID + n0];
        c0r[rr * 2 + 1] = g_c0[m * HID + n0 + 1];
    }

    // invariant staging coords
    const int rowA = tid >> 1;
    const int cA   = (tid & 1) * 2;
    const size_t gAo = (size_t)rowA * HID + cA * 8;
    const u32  dA    = sb + rowA * 80 + cA * 16;
    const int ntB = tid >> 6, jB = (tid >> 5) & 1, lnB = tid & 31;
    const size_t bBase = ((size_t)(ntB * 128 + bx) * 64 + jB) * 32 + lnB;
    const u32  dB    = sb + PS_B + (((ntB * 2 + jB) * 32 + lnB) << 4);
    const u32 aFragBase = sb + (w * 16 + (lane & 15)) * 80 + ((lane >> 4) * 16);

#pragma unroll 1
    for (int t = 0; t < STEPS; t++) {
        const int do_l0 = (t < STEPS - 1);
        const __half* AhA = g_h0hi[(t + 1) & 1];
        const __half* AlA = g_h0lo[(t + 1) & 1];
        const __half* AhB = g_h1hi[t & 1];
        const __half* AlB = g_h1lo[t & 1];

        float acc1[4][4], acc0[4][4];
#pragma unroll
        for (int i = 0; i < 4; i++)
#pragma unroll
            for (int j = 0; j < 4; j++) { acc1[i][j] = 0.f; acc0[i][j] = 0.f; }

        auto issue = [&](int kt) {
            int s = kt & 3;
            bool pa = kt < 32;
            int kk = pa ? kt : kt - 32;
            const __half* Ah = pa ? AhA : AhB;
            const __half* Al = pa ? AlA : AlB;
            size_t ga = gAo + kk * 32;
            u32 da = dA + s * 10240;
            cpa16(da,               Ah + ga);
            cpa16(da + 16,          Ah + ga + 8);
            cpa16(da + PS_ALO,      Al + ga);
            cpa16(da + PS_ALO + 16, Al + ga + 8);
            size_t bsrc = bBase + (size_t)kk * 64;
            u32 db = dB + s * 8192;
            if (pa) {
                cpa16(db, g_wih1p + bsrc);
                if (do_l0) cpa16(db + 4096, g_whh0p + bsrc);
            } else {
                cpa16(db, g_whh1p + bsrc);
            }
        };

        issue(0); cpa_commit();
        issue(1); cpa_commit();
        issue(2); cpa_commit();

#pragma unroll 1
        for (int kt = 0; kt < 64; kt++) {
            int s = kt & 3;
            cpa_wait<2>();
            __syncthreads();
            if (kt + 3 < 64) issue(kt + 3);
            cpa_commit();
            bool pa = kt < 32;
            const uint4* bst = (const uint4*)(smem + PS_B + s * 8192);
            const u32 aF = aFragBase + s * 10240;
#pragma unroll
            for (int sub = 0; sub < 2; sub++) {
                u32 ah[4], al[4];
                ldm4(ah, aF + sub * 32);
                ldm4(al, aF + PS_ALO + sub * 32);
#pragma unroll
                for (int nt = 0; nt < 4; nt++) {
                    uint4 bp = bst[(nt * 2 + sub) * 32 + lane];
                    u32 bh[2] = {bp.x, bp.y}, bl[2] = {bp.z, bp.w};
                    mma_f16(acc1[nt], ah, bh);
                    mma_f16(acc1[nt], al, bh);
                    mma_f16(acc1[nt], ah, bl);
                }
                if (pa && do_l0) {
#pragma unroll
                    for (int nt = 0; nt < 4; nt++) {
                        uint4 bp = bst[256 + (nt * 2 + sub) * 32 + lane];
                        u32 bh[2] = {bp.x, bp.y}, bl[2] = {bp.z, bp.w};
                        mma_f16(acc0[nt], ah, bh);
                        mma_f16(acc0[nt], al, bh);
                        mma_f16(acc0[nt], ah, bl);
                    }
                }
            }
        }
        cpa_wait<0>();

        // ---- L1(t) epilogue: c1 in regs, pack half2 stores ----
        {
            __half* Hhi = g_h1hi[(t + 1) & 1];
            __half* Hlo = g_h1lo[(t + 1) & 1];
#pragma unroll
            for (int rr = 0; rr < 2; rr++) {
                int m = w * 16 + qr + rr * 8;
                __half hh[2], hl[2];
#pragma unroll
                for (int e = 0; e < 2; e++) {
                    int ri = rr * 2 + e;
                    float iv = acc1[0][ri] + bs[0][e];
                    float fv = acc1[1][ri] + bs[1][e];
                    float gv = acc1[2][ri] + bs[2][e];
                    float ov = acc1[3][ri] + bs[3][e];
                    float cn = sigm(fv) * c1r[ri] + sigm(iv) * tanhf(gv);
                    c1r[ri] = cn;
                    float h = sigm(ov) * tanhf(cn);
                    hh[e] = __float2half_rn(h);
                    hl[e] = __float2half_rn(h - __half2float(hh[e]));
                }
                *(__half2*)&Hhi[m * HID + n0] = __halves2half2(hh[0], hh[1]);
                *(__half2*)&Hlo[m * HID + n0] = __halves2half2(hl[0], hl[1]);
            }
        }
        // ---- L0(t+1) epilogue ----
        if (do_l0) {
            const float* xp = g_xproj + (size_t)(t + 1) * BATCH * G4;
            __half* Hhi = g_h0hi[t & 1];
            __half* Hlo = g_h0lo[t & 1];
#pragma unroll
            for (int rr = 0; rr < 2; rr++) {
                int m = w * 16 + qr + rr * 8;
                const float* xr = xp + (size_t)m * G4 + n0;
                float2 xi = *(const float2*)(xr);
                float2 xf = *(const float2*)(xr + 1024);
                float2 xg = *(const float2*)(xr + 2048);
                float2 xo = *(const float2*)(xr + 3072);
                __half hh[2], hl[2];
#pragma unroll
                for (int e = 0; e < 2; e++) {
                    int ri = rr * 2 + e;
                    float iv = acc0[0][ri] + (e ? xi.y : xi.x);
                    float fv = acc0[1][ri] + (e ? xf.y : xf.x);
                    float gv = acc0[2][ri] + (e ? xg.y : xg.x);
                    float ov = acc0[3][ri] + (e ? xo.y : xo.x);
                    float cn = sigm(fv) * c0r[ri] + sigm(iv) * tanhf(gv);
                    c0r[ri] = cn;
                    float h = sigm(ov) * tanhf(cn);
                    hh[e] = __float2half_rn(h);
                    hl[e] = __float2half_rn(h - __half2float(hh[e]));
                }
                *(__half2*)&Hhi[m * HID + n0] = __halves2half2(hh[0], hh[1]);
                *(__half2*)&Hlo[m * HID + n0] = __halves2half2(hl[0], hl[1]);
            }
        }
        grid_barrier(t);
    }
}

// ===========================================================================
// xproj v2: 256 threads, grid (64 colblocks, 64 times), warp = 16 rows x 64 cols
// ===========================================================================
__global__ void __launch_bounds__(256) xproj_kernel(
    const float* __restrict__ xs,
    const float* __restrict__ bih0, const float* __restrict__ bhh0)
{
    __shared__ __align__(16) __half sAhi[2][128][24];
    __shared__ __align__(16) __half sAlo[2][128][24];
    __shared__ uint4 sB[2][8][32];
    const int tid = threadIdx.x;
    const int nbx = blockIdx.x;   // 64-col block
    const int mb  = blockIdx.y;   // time index
    const int w = tid >> 5, lane = tid & 31, qr = lane >> 2, qc = lane & 3;

    float acc[8][4];
#pragma unroll
    for (int j = 0; j < 8; j++)
#pragma unroll
        for (int k = 0; k < 4; k++) acc[j][k] = 0.f;

    const int srow = tid >> 1, sseg = tid & 1;
    const float* arow = xs + (size_t)(srow * 128 + TOFF + mb) * DIN + sseg * 8;

    float4 rf0, rf1;
    uint4 rb;
    auto ld = [&](int kt) {
        rf0 = *(const float4*)(arow + kt * 16);
        rf1 = *(const float4*)(arow + kt * 16 + 4);
        rb = g_wih0p[((size_t)(nbx * 8 + w) * 32 + kt) * 32 + lane];
    };
    ld(0);
#pragma unroll 1
    for (int kt = 0; kt < 32; kt++) {
        int s = kt & 1;
        __half2* dh = (__half2*)&sAhi[s][srow][sseg * 8];
        __half2* dl = (__half2*)&sAlo[s][srow][sseg * 8];
        float v[8] = {rf0.x, rf0.y, rf0.z, rf0.w, rf1.x, rf1.y, rf1.z, rf1.w};
#pragma unroll
        for (int p = 0; p < 4; p++) {
            float x0 = v[p * 2], x1 = v[p * 2 + 1];
            __half a0 = __float2half_rn(x0), a1 = __float2half_rn(x1);
            dh[p] = __halves2half2(a0, a1);
            dl[p] = __halves2half2(__float2half_rn(x0 - __half2float(a0)),
                                   __float2half_rn(x1 - __half2float(a1)));
        }
        sB[s][w][lane] = rb;
        __syncthreads();
        if (kt + 1 < 32) ld(kt + 1);
        {
            const int r = w * 16 + qr;
            u32 ah[4], al[4];
            ah[0] = *(const u32*)&sAhi[s][r][qc * 2];
            ah[1] = *(const u32*)&sAhi[s][r + 8][qc * 2];
            ah[2] = *(const u32*)&sAhi[s][r][qc * 2 + 8];
            ah[3] = *(const u32*)&sAhi[s][r + 8][qc * 2 + 8];
            al[0] = *(const u32*)&sAlo[s][r][qc * 2];
            al[1] = *(const u32*)&sAlo[s][r + 8][qc * 2];
            al[2] = *(const u32*)&sAlo[s][r][qc * 2 + 8];
            al[3] = *(const u32*)&sAlo[s][r + 8][qc * 2 + 8];
#pragma unroll
            for (int nt = 0; nt < 8; nt++) {
                uint4 bp = sB[s][nt][lane];
                u32 bh[2] = {bp.x, bp.y}, bl[2] = {bp.z, bp.w};
                mma_f16(acc[nt], ah, bh);
                mma_f16(acc[nt], al, bh);
                mma_f16(acc[nt], ah, bl);
            }
        }
        __syncthreads();
    }

    const int m0g = mb * 128 + w * 16 + qr;
#pragma unroll
    for (int nt = 0; nt < 8; nt++) {
        int colb = nbx * 64 + nt * 8 + qc * 2;
        float bv0 = bih0[colb] + bhh0[colb];
        float bv1 = bih0[colb + 1] + bhh0[colb + 1];
        *(float2*)&g_xproj[(size_t)m0g * G4 + colb] =
            make_float2(acc[nt][0] + bv0, acc[nt][1] + bv1);
        *(float2*)&g_xproj[(size_t)(m0g + 8) * G4 + colb] =
            make_float2(acc[nt][2] + bv0, acc[nt][3] + bv1);
    }
}

// ---------------- classifier (unchanged) ------------------------------------
__global__ void __launch_bounds__(256) classifier_kernel(
    const float* __restrict__ Wcls, const float* __restrict__ bcls,
    const float* __restrict__ dropu, float* __restrict__ out)
{
    int gw = (blockIdx.x * blockDim.x + threadIdx.x) >> 5;
    int lane = threadIdx.x & 31;
    int j = gw >> 5;
    int b0 = (gw & 31) * 4;
    const __half* hi = g_h1hi[0];
    const __half* lo = g_h1lo[0];

    float acc[4] = {0.f, 0.f, 0.f, 0.f};
#pragma unroll
    for (int it = 0; it < 8; ++it) {
        int h = it * 128 + lane * 4;
        float4 wv = *(const float4*)&Wcls[(size_t)j * HID + h];
#pragma unroll
        for (int bi = 0; bi < 4; ++bi) {
            int b = b0 + bi;
            int idx = b * HID + h;
            __half2 a0 = *(const __half2*)&hi[idx];
            __half2 a1 = *(const __half2*)&hi[idx + 2];
            __half2 c0 = *(const __half2*)&lo[idx];
            __half2 c1 = *(const __half2*)&lo[idx + 2];
            float2 f0 = __half22float2(a0), f1 = __half22float2(a1);
            float2 g0 = __half22float2(c0), g1 = __half22float2(c1);
            float x0 = f0.x + g0.x, x1 = f0.y + g0.y;
            float x2 = f1.x + g1.x, x3 = f1.y + g1.y;
            float4 u = *(const float4*)&dropu[(size_t)b * HID + h];
            acc[bi] += (u.x > 0.5f ? x0 : 0.f) * wv.x
                     + (u.y > 0.5f ? x1 : 0.f) * wv.y
                     + (u.z > 0.5f ? x2 : 0.f) * wv.z
                     + (u.w > 0.5f ? x3 : 0.f) * wv.w;
        }
    }
#pragma unroll
    for (int bi = 0; bi < 4; ++bi) {
        float v = acc[bi];
#pragma unroll
        for (int off = 16; off; off >>= 1)
            v += __shfl_xor_sync(0xffffffffu, v, off);
        if (lane == 0)
            out[(size_t)(b0 + bi) * 1000 + j] = 2.0f * v + bcls[j];
    }
}

// ---------------- launch ----------------------------------------------------
extern "C" void kernel_launch(void* const* d_in, const int* in_sizes, int n_in,
                              void* d_out, int out_size)
{
    const float* xs    = (const float*)d_in[0];
    const float* Wih0  = (const float*)d_in[1];
    const float* Whh0  = (const float*)d_in[2];
    const float* bih0  = (const float*)d_in[3];
    const float* bhh0  = (const float*)d_in[4];
    const float* Wih1  = (const float*)d_in[5];
    const float* Whh1  = (const float*)d_in[6];
    const float* bih1  = (const float*)d_in[7];
    const float* bhh1  = (const float*)d_in[8];
    const float* Wcls  = (const float*)d_in[9];
    const float* bcls  = (const float*)d_in[10];
    const float* dropu = (const float*)d_in[11];
    float* out = (float*)d_out;

    cudaFuncSetAttribute(step_persist, cudaFuncAttributeMaxDynamicSharedMemorySize, PS_TOTAL);

    // launch order chosen so step_persist is the 6th launch (ncu -s 5 -c 1)
    init_states<<<(BATCH * HID + 255) / 256, 256>>>();
    pack_a<<<(2 * PACK_N64) / 256, 256>>>(Whh0, Wih1);
    pack_b<<<(PACK_N64 + PACK_N32) / 256, 256>>>(Whh1, Wih0);
    xproj_kernel<<<dim3(64, 64), 256>>>(xs, bih0, bhh0);
    l0_first<<<(BATCH * HID + 255) / 256, 256>>>();
    step_persist<<<128, 256, PS_TOTAL>>>(bih1, bhh1);
    classifier_kernel<<<4000, 256>>>(Wcls, bcls, dropu, out);
}